// round 1
// baseline (speedup 1.0000x reference)
#include <cuda_runtime.h>
#include <math.h>

// Problem constants
#define NIMG 128
#define HH 28
#define WW 28
#define OCH 256
#define C1 537      // 512 features + 25 pooled
#define CF 512
#define CP 25

// Tap offsets (flattened 3x3 index t -> (dh, dw))
// TAPS = [(-1,-3),(-1,-1),(-1,1),(0,0),(0,2),(-2,1),(0,-1),(2,0),(3,1)]
// dh in [-2,3], dw in [-3,2]

#define HALO_R 12          // 7 output rows + dh range [-2,3] => 12 rows
#define HALO_C 33          // 28 cols + dw range [-3,2] => 33 cols
#define CK 8               // channels per smem chunk
#define TO 64              // output-channel tile
#define TS 196             // spatial tile: 7 rows * 28 cols

// Scratch (allocation-free contract: __device__ globals)
__device__ float g_pooled[NIMG * CP * HH * WW];                 // 10 MB
__device__ float g_x1[(size_t)NIMG * OCH * HH * WW];            // 103 MB
__device__ float g_x2[(size_t)NIMG * OCH * HH * WW];            // 103 MB
__device__ float g_w1t[C1 * 9 * OCH];                           // 5 MB
__device__ float g_w2t[OCH * 9 * OCH];
__device__ float g_w3t[OCH * 9 * OCH];
__device__ float g_w4t[OCH * 9 * OCH];

// ---------------------------------------------------------------------------
// 4x4 max pool: fine_segm [128,25,112,112] -> g_pooled [128,25,28,28]
// ---------------------------------------------------------------------------
__global__ void pool_kernel(const float* __restrict__ in, float* __restrict__ out) {
    int idx = blockIdx.x * blockDim.x + threadIdx.x;
    const int total = NIMG * CP * HH * WW;
    if (idx >= total) return;
    int plane = idx / (HH * WW);          // n*25 + p
    int rem   = idx % (HH * WW);
    int r = rem / WW, c = rem % WW;
    const float* p = in + ((size_t)plane * 112 + r * 4) * 112 + c * 4;
    float m = -INFINITY;
#pragma unroll
    for (int i = 0; i < 4; i++)
#pragma unroll
        for (int j = 0; j < 4; j++)
            m = fmaxf(m, p[i * 112 + j]);
    out[idx] = m;
}

// ---------------------------------------------------------------------------
// Repack weights [O,C,3,3] -> [C][9][O] (coalesced smem fills later)
// ---------------------------------------------------------------------------
__global__ void repack_kernel(const float* __restrict__ w, float* __restrict__ wt, int C) {
    int idx = blockIdx.x * blockDim.x + threadIdx.x;
    if (idx >= C * 9 * OCH) return;
    int o  = idx & (OCH - 1);
    int ct = idx >> 8;              // OCH = 256
    int c  = ct / 9;
    int t  = ct - c * 9;
    wt[idx] = w[((size_t)o * C + c) * 9 + t];
}

// ---------------------------------------------------------------------------
// One deform-conv layer: out[n,o,h,w] = relu( sum_{c,t} x[n,c,h+dh,w+dw]*w[o,c,t] )
// Input channels split across two tensors (xA: first CA channels, xB: rest)
// so layer 1 can read features + pooled without a 215 MB concat copy.
// Block: 256 threads; tile 64 O x 196 spatial (7 rows); K-chunks of 8 channels.
// Thread: so = tid>>5 (warp id) -> o = oBase + so*8 + j (j<8, per-thread contiguous,
// float4 weight loads); ss = tid&31 -> s = ss + 32*i (i<7, lane-contiguous spatial,
// coalesced stores, conflict-free LDS).
// ---------------------------------------------------------------------------
__global__ __launch_bounds__(256, 2)
void conv_layer(const float* __restrict__ xA, int CA,
                const float* __restrict__ xB, int CB,
                const float* __restrict__ wt,   // [C][9][OCH]
                int C,
                float* __restrict__ out)
{
    __shared__ float xs[CK][HALO_R * HALO_C];   // 8 * 396 floats = 12.4 KB
    __shared__ float ws[CK][9][TO];             // 8 * 9 * 64     = 18.0 KB

    const int tid   = threadIdx.x;
    const int n     = blockIdx.z;
    const int oBase = blockIdx.y * TO;
    const int r0    = blockIdx.x * 7;           // first output row of this tile

    const int ss = tid & 31;
    const int so = tid >> 5;                    // warp id: constant per warp

    // Per-thread spatial positions (s = ss + 32*i)
    int  sbase[7];
    int  srow[7], scol[7];
    bool svalid[7];
#pragma unroll
    for (int i = 0; i < 7; i++) {
        int s = ss + 32 * i;
        svalid[i] = (s < TS);
        int r = s / WW, c = s - r * WW;
        srow[i] = r; scol[i] = c;
        // base index into padded halo plane; 69 = safe dummy (tap offsets in [-65,100])
        sbase[i] = svalid[i] ? ((r + 2) * HALO_C + (c + 3)) : 69;
    }

    float acc[7][8];
#pragma unroll
    for (int i = 0; i < 7; i++)
#pragma unroll
        for (int j = 0; j < 8; j++) acc[i][j] = 0.f;

    const int tap_dh[9] = {-1, -1, -1, 0, 0, -2, 0, 2, 3};
    const int tap_dw[9] = {-3, -1, 1, 0, 2, 1, -1, 0, 1};

    for (int c0 = 0; c0 < C; c0 += CK) {
        const int ck = min(CK, C - c0);
        __syncthreads();

        // ---- load input halo planes (zero padded) ----
        const int halo_elems = ck * HALO_R * HALO_C;
        for (int idx = tid; idx < halo_elems; idx += 256) {
            int c   = idx / (HALO_R * HALO_C);
            int rem = idx - c * (HALO_R * HALO_C);
            int rr  = rem / HALO_C;
            int cc  = rem - rr * HALO_C;
            int gr  = r0 - 2 + rr;
            int gc  = cc - 3;
            float v = 0.f;
            if ((unsigned)gr < (unsigned)HH && (unsigned)gc < (unsigned)WW) {
                int gch = c0 + c;
                const float* p = (gch < CA)
                    ? xA + (((size_t)n * CA + gch) * HH + gr) * WW + gc
                    : xB + (((size_t)n * CB + (gch - CA)) * HH + gr) * WW + gc;
                v = *p;
            }
            xs[c][rem] = v;
        }

        // ---- load weight tile (coalesced: wt is [C][9][O]) ----
        const int w_elems = ck * 9 * TO;
        for (int idx = tid; idx < w_elems; idx += 256) {
            int c   = idx / (9 * TO);
            int rem = idx - c * (9 * TO);
            int t   = rem / TO;
            int o   = rem - t * TO;
            ws[c][t][o] = wt[((size_t)(c0 + c) * 9 + t) * OCH + oBase + o];
        }
        __syncthreads();

        // ---- FMA main loop ----
        for (int c = 0; c < ck; c++) {
#pragma unroll
            for (int t = 0; t < 9; t++) {
                const int toff = tap_dh[t] * HALO_C + tap_dw[t];
                // 8 weights for this (c,t), contiguous: two float4 LDS
                const float4* wp = reinterpret_cast<const float4*>(&ws[c][t][so * 8]);
                float4 w0 = wp[0];
                float4 w1 = wp[1];
                float wv[8] = {w0.x, w0.y, w0.z, w0.w, w1.x, w1.y, w1.z, w1.w};
#pragma unroll
                for (int i = 0; i < 7; i++) {
                    float xv = xs[c][sbase[i] + toff];
#pragma unroll
                    for (int j = 0; j < 8; j++)
                        acc[i][j] = fmaf(xv, wv[j], acc[i][j]);
                }
            }
        }
    }

    // ---- store with ReLU (coalesced: lanes cover consecutive spatial) ----
#pragma unroll
    for (int i = 0; i < 7; i++) {
        if (!svalid[i]) continue;
        int r = r0 + srow[i];
        int c = scol[i];
#pragma unroll
        for (int j = 0; j < 8; j++) {
            int o = oBase + so * 8 + j;
            out[(((size_t)n * OCH + o) * HH + r) * WW + c] = fmaxf(acc[i][j], 0.f);
        }
    }
}

// ---------------------------------------------------------------------------
extern "C" void kernel_launch(void* const* d_in, const int* in_sizes, int n_in,
                              void* d_out, int out_size)
{
    const float* features  = (const float*)d_in[0];   // [128,512,28,28]
    const float* fine_segm = (const float*)d_in[1];   // [128,25,112,112]
    const float* w1 = (const float*)d_in[2];          // [256,537,3,3]
    const float* w2 = (const float*)d_in[3];          // [256,256,3,3]
    const float* w3 = (const float*)d_in[4];
    const float* w4 = (const float*)d_in[5];
    float* out = (float*)d_out;                       // [128,256,28,28]

    float *pooled, *x1, *x2, *w1t, *w2t, *w3t, *w4t;
    cudaGetSymbolAddress((void**)&pooled, g_pooled);
    cudaGetSymbolAddress((void**)&x1, g_x1);
    cudaGetSymbolAddress((void**)&x2, g_x2);
    cudaGetSymbolAddress((void**)&w1t, g_w1t);
    cudaGetSymbolAddress((void**)&w2t, g_w2t);
    cudaGetSymbolAddress((void**)&w3t, g_w3t);
    cudaGetSymbolAddress((void**)&w4t, g_w4t);

    // Stage 0: pooling + weight repack (independent, cheap)
    {
        int total = NIMG * CP * HH * WW;
        pool_kernel<<<(total + 255) / 256, 256>>>(fine_segm, pooled);
    }
    repack_kernel<<<(C1 * 9 * OCH + 255) / 256, 256>>>(w1, w1t, C1);
    repack_kernel<<<(OCH * 9 * OCH + 255) / 256, 256>>>(w2, w2t, OCH);
    repack_kernel<<<(OCH * 9 * OCH + 255) / 256, 256>>>(w3, w3t, OCH);
    repack_kernel<<<(OCH * 9 * OCH + 255) / 256, 256>>>(w4, w4t, OCH);

    dim3 grid(4, OCH / TO, NIMG);   // 4 spatial tiles x 4 o-tiles x 128 images
    dim3 block(256);

    // Layer 1: features (512 ch) + pooled (25 ch) -> x1
    conv_layer<<<grid, block>>>(features, CF, pooled, CP, w1t, C1, x1);
    // Layer 2: x1 -> x2
    conv_layer<<<grid, block>>>(x1, OCH, x1, 1, w2t, OCH, x2);
    // Layer 3: x2 -> x1
    conv_layer<<<grid, block>>>(x2, OCH, x2, 1, w3t, OCH, x1);
    // Layer 4: x1 -> out
    conv_layer<<<grid, block>>>(x1, OCH, x1, 1, w4t, OCH, out);
}

// round 2
// speedup vs baseline: 1.0367x; 1.0367x over previous
#include <cuda_runtime.h>
#include <math.h>

// Problem constants
#define NIMG 128
#define HH 28
#define WW 28
#define OCH 256
#define C1 537      // 512 features + 25 pooled
#define CF 512
#define CP 25

// TAPS = [(-1,-3),(-1,-1),(-1,1),(0,0),(0,2),(-2,1),(0,-1),(2,0),(3,1)]
// dh in [-2,3], dw in [-3,2]

#define HALO_R 12          // 7 output rows + dh range [-2,3]
#define HALO_C 33          // 28 cols + dw range [-3,2]
#define CK 8               // channels per smem chunk
#define TO 64              // output-channel tile
#define TS 196             // spatial tile: 7 rows * 28 cols

// Scratch (allocation-free contract: __device__ globals)
__device__ float g_pooled[NIMG * CP * HH * WW];
__device__ float g_x1[(size_t)NIMG * OCH * HH * WW];
__device__ float g_x2[(size_t)NIMG * OCH * HH * WW];
__device__ float g_w1t[C1 * 9 * OCH];
__device__ float g_w2t[OCH * 9 * OCH];
__device__ float g_w3t[OCH * 9 * OCH];
__device__ float g_w4t[OCH * 9 * OCH];

// ---------------------------------------------------------------------------
__global__ void pool_kernel(const float* __restrict__ in, float* __restrict__ out) {
    int idx = blockIdx.x * blockDim.x + threadIdx.x;
    const int total = NIMG * CP * HH * WW;
    if (idx >= total) return;
    int plane = idx / (HH * WW);
    int rem   = idx % (HH * WW);
    int r = rem / WW, c = rem % WW;
    const float* p = in + ((size_t)plane * 112 + r * 4) * 112 + c * 4;
    float m = -INFINITY;
#pragma unroll
    for (int i = 0; i < 4; i++)
#pragma unroll
        for (int j = 0; j < 4; j++)
            m = fmaxf(m, p[i * 112 + j]);
    out[idx] = m;
}

// ---------------------------------------------------------------------------
__global__ void repack_kernel(const float* __restrict__ w, float* __restrict__ wt, int C) {
    int idx = blockIdx.x * blockDim.x + threadIdx.x;
    if (idx >= C * 9 * OCH) return;
    int o  = idx & (OCH - 1);
    int ct = idx >> 8;
    int c  = ct / 9;
    int t  = ct - c * 9;
    wt[idx] = w[((size_t)o * C + c) * 9 + t];
}

// ---------------------------------------------------------------------------
// Deform-conv layer with packed f32x2 FMA (FFMA2) inner loop.
// Each thread: 8 output channels (4 packed pairs) x 7 spatial positions.
// ---------------------------------------------------------------------------
__global__ __launch_bounds__(256, 2)
void conv_layer(const float* __restrict__ xA, int CA,
                const float* __restrict__ xB, int CB,
                const float* __restrict__ wt,   // [C][9][OCH]
                int C,
                float* __restrict__ out)
{
    __shared__ float xs[CK][HALO_R * HALO_C];   // 12.4 KB
    __shared__ float ws[CK][9][TO];             // 18.0 KB

    const int tid   = threadIdx.x;
    const int n     = blockIdx.z;
    const int oBase = blockIdx.y * TO;
    const int r0    = blockIdx.x * 7;

    const int ss = tid & 31;
    const int so = tid >> 5;

    int  sbase[7];
    int  srow[7], scol[7];
    bool svalid[7];
#pragma unroll
    for (int i = 0; i < 7; i++) {
        int s = ss + 32 * i;
        svalid[i] = (s < TS);
        int r = s / WW, c = s - r * WW;
        srow[i] = r; scol[i] = c;
        sbase[i] = svalid[i] ? ((r + 2) * HALO_C + (c + 3)) : 69;  // 69: safe dummy
    }

    // Packed accumulators: acc2[i][j] holds outputs o = so*8 + 2j (lo) and +1 (hi)
    unsigned long long acc2[7][4];
#pragma unroll
    for (int i = 0; i < 7; i++)
#pragma unroll
        for (int j = 0; j < 4; j++) acc2[i][j] = 0ull;

    const int tap_dh[9] = {-1, -1, -1, 0, 0, -2, 0, 2, 3};
    const int tap_dw[9] = {-3, -1, 1, 0, 2, 1, -1, 0, 1};

    for (int c0 = 0; c0 < C; c0 += CK) {
        const int ck = min(CK, C - c0);
        __syncthreads();

        // ---- load input halo planes (zero padded) ----
        const int halo_elems = ck * HALO_R * HALO_C;
        for (int idx = tid; idx < halo_elems; idx += 256) {
            int c   = idx / (HALO_R * HALO_C);
            int rem = idx - c * (HALO_R * HALO_C);
            int rr  = rem / HALO_C;
            int cc  = rem - rr * HALO_C;
            int gr  = r0 - 2 + rr;
            int gc  = cc - 3;
            float v = 0.f;
            if ((unsigned)gr < (unsigned)HH && (unsigned)gc < (unsigned)WW) {
                int gch = c0 + c;
                const float* p = (gch < CA)
                    ? xA + (((size_t)n * CA + gch) * HH + gr) * WW + gc
                    : xB + (((size_t)n * CB + (gch - CA)) * HH + gr) * WW + gc;
                v = *p;
            }
            xs[c][rem] = v;
        }

        // ---- load weight tile (coalesced: wt is [C][9][O]) ----
        const int w_elems = ck * 9 * TO;
        for (int idx = tid; idx < w_elems; idx += 256) {
            int c   = idx / (9 * TO);
            int rem = idx - c * (9 * TO);
            int t   = rem / TO;
            int o   = rem - t * TO;
            ws[c][t][o] = wt[((size_t)(c0 + c) * 9 + t) * OCH + oBase + o];
        }
        __syncthreads();

        // ---- packed-FMA main loop ----
        for (int c = 0; c < ck; c++) {
#pragma unroll
            for (int t = 0; t < 9; t++) {
                const int toff = tap_dh[t] * HALO_C + tap_dw[t];
                // 8 contiguous weights -> 4 packed f32x2 pairs via two LDS.128
                const ulonglong2* wp = reinterpret_cast<const ulonglong2*>(&ws[c][t][so * 8]);
                ulonglong2 wa = wp[0];
                ulonglong2 wb = wp[1];
                unsigned long long w2[4] = {wa.x, wa.y, wb.x, wb.y};
#pragma unroll
                for (int i = 0; i < 7; i++) {
                    float xv = xs[c][sbase[i] + toff];
                    unsigned long long xv2;
                    asm("mov.b64 %0, {%1, %1};" : "=l"(xv2) : "f"(xv));
#pragma unroll
                    for (int j = 0; j < 4; j++)
                        asm("fma.rn.f32x2 %0, %1, %2, %0;"
                            : "+l"(acc2[i][j]) : "l"(xv2), "l"(w2[j]));
                }
            }
        }
    }

    // ---- store with ReLU ----
#pragma unroll
    for (int i = 0; i < 7; i++) {
        if (!svalid[i]) continue;
        int r = r0 + srow[i];
        int c = scol[i];
#pragma unroll
        for (int j = 0; j < 4; j++) {
            float lo, hi;
            asm("mov.b64 {%0, %1}, %2;" : "=f"(lo), "=f"(hi) : "l"(acc2[i][j]));
            int o = oBase + so * 8 + 2 * j;
            size_t base = (((size_t)n * OCH + o) * HH + r) * WW + c;
            out[base]            = fmaxf(lo, 0.f);
            out[base + HH * WW]  = fmaxf(hi, 0.f);
        }
    }
}

// ---------------------------------------------------------------------------
extern "C" void kernel_launch(void* const* d_in, const int* in_sizes, int n_in,
                              void* d_out, int out_size)
{
    const float* features  = (const float*)d_in[0];   // [128,512,28,28]
    const float* fine_segm = (const float*)d_in[1];   // [128,25,112,112]
    const float* w1 = (const float*)d_in[2];          // [256,537,3,3]
    const float* w2 = (const float*)d_in[3];          // [256,256,3,3]
    const float* w3 = (const float*)d_in[4];
    const float* w4 = (const float*)d_in[5];
    float* out = (float*)d_out;                       // [128,256,28,28]

    float *pooled, *x1, *x2, *w1t, *w2t, *w3t, *w4t;
    cudaGetSymbolAddress((void**)&pooled, g_pooled);
    cudaGetSymbolAddress((void**)&x1, g_x1);
    cudaGetSymbolAddress((void**)&x2, g_x2);
    cudaGetSymbolAddress((void**)&w1t, g_w1t);
    cudaGetSymbolAddress((void**)&w2t, g_w2t);
    cudaGetSymbolAddress((void**)&w3t, g_w3t);
    cudaGetSymbolAddress((void**)&w4t, g_w4t);

    {
        int total = NIMG * CP * HH * WW;
        pool_kernel<<<(total + 255) / 256, 256>>>(fine_segm, pooled);
    }
    repack_kernel<<<(C1 * 9 * OCH + 255) / 256, 256>>>(w1, w1t, C1);
    repack_kernel<<<(OCH * 9 * OCH + 255) / 256, 256>>>(w2, w2t, OCH);
    repack_kernel<<<(OCH * 9 * OCH + 255) / 256, 256>>>(w3, w3t, OCH);
    repack_kernel<<<(OCH * 9 * OCH + 255) / 256, 256>>>(w4, w4t, OCH);

    dim3 grid(4, OCH / TO, NIMG);
    dim3 block(256);

    conv_layer<<<grid, block>>>(features, CF, pooled, CP, w1t, C1, x1);
    conv_layer<<<grid, block>>>(x1, OCH, x1, 1, w2t, OCH, x2);
    conv_layer<<<grid, block>>>(x2, OCH, x2, 1, w3t, OCH, x1);
    conv_layer<<<grid, block>>>(x1, OCH, x1, 1, w4t, OCH, out);
}

// round 4
// speedup vs baseline: 1.0380x; 1.0013x over previous
#include <cuda_runtime.h>
#include <math.h>

// Problem constants
#define NIMG 128
#define HH 28
#define WW 28
#define OCH 256
#define C1 537      // 512 features + 25 pooled
#define CF 512
#define CP 25

// TAPS = [(-1,-3),(-1,-1),(-1,1),(0,0),(0,2),(-2,1),(0,-1),(2,0),(3,1)]
// dh in [-2,3], dw in [-3,2]

#define HALO_R 12          // 7 output rows + dh range [-2,3]
#define HALO_C 33          // 28 cols + dw range [-3,2]
#define CK 8               // channels per smem chunk
#define TO 64              // output-channel tile
#define TS 196             // spatial tile: 7 rows * 28 cols

// Scratch (allocation-free contract: __device__ globals)
__device__ float g_pooled[NIMG * CP * HH * WW];
__device__ float g_x1[(size_t)NIMG * OCH * HH * WW];
__device__ float g_x2[(size_t)NIMG * OCH * HH * WW];
__device__ float g_w1t[C1 * 9 * OCH];
__device__ float g_w2t[OCH * 9 * OCH];
__device__ float g_w3t[OCH * 9 * OCH];
__device__ float g_w4t[OCH * 9 * OCH];

// ---------------------------------------------------------------------------
__global__ void pool_kernel(const float* __restrict__ in, float* __restrict__ out) {
    int idx = blockIdx.x * blockDim.x + threadIdx.x;
    const int total = NIMG * CP * HH * WW;
    if (idx >= total) return;
    int plane = idx / (HH * WW);
    int rem   = idx % (HH * WW);
    int r = rem / WW, c = rem % WW;
    const float* p = in + ((size_t)plane * 112 + r * 4) * 112 + c * 4;
    float m = -INFINITY;
#pragma unroll
    for (int i = 0; i < 4; i++)
#pragma unroll
        for (int j = 0; j < 4; j++)
            m = fmaxf(m, p[i * 112 + j]);
    out[idx] = m;
}

// ---------------------------------------------------------------------------
__global__ void repack_kernel(const float* __restrict__ w, float* __restrict__ wt, int C) {
    int idx = blockIdx.x * blockDim.x + threadIdx.x;
    if (idx >= C * 9 * OCH) return;
    int o  = idx & (OCH - 1);
    int ct = idx >> 8;
    int c  = ct / 9;
    int t  = ct - c * 9;
    wt[idx] = w[((size_t)o * C + c) * 9 + t];
}

// ---------------------------------------------------------------------------
// Deform-conv layer with packed f32x2 FMA (FFMA2) inner loop.
// Each thread: 8 output channels (4 packed pairs) x 7 spatial positions.
// ---------------------------------------------------------------------------
__global__ __launch_bounds__(256, 2)
void conv_layer(const float* __restrict__ xA, int CA,
                const float* __restrict__ xB, int CB,
                const float* __restrict__ wt,   // [C][9][OCH]
                int C,
                float* __restrict__ out)
{
    __shared__ float xs[CK][HALO_R * HALO_C];   // 12.4 KB
    __shared__ float ws[CK][9][TO];             // 18.0 KB

    const int tid   = threadIdx.x;
    const int n     = blockIdx.z;
    const int oBase = blockIdx.y * TO;
    const int r0    = blockIdx.x * 7;

    const int ss = tid & 31;
    const int so = tid >> 5;

    int  sbase[7];
    int  srow[7], scol[7];
    bool svalid[7];
#pragma unroll
    for (int i = 0; i < 7; i++) {
        int s = ss + 32 * i;
        svalid[i] = (s < TS);
        int r = s / WW, c = s - r * WW;
        srow[i] = r; scol[i] = c;
        sbase[i] = svalid[i] ? ((r + 2) * HALO_C + (c + 3)) : 69;  // 69: safe dummy
    }

    // Packed accumulators: acc2[i][j] holds outputs o = so*8 + 2j (lo) and +1 (hi)
    unsigned long long acc2[7][4];
#pragma unroll
    for (int i = 0; i < 7; i++)
#pragma unroll
        for (int j = 0; j < 4; j++) acc2[i][j] = 0ull;

    const int tap_dh[9] = {-1, -1, -1, 0, 0, -2, 0, 2, 3};
    const int tap_dw[9] = {-3, -1, 1, 0, 2, 1, -1, 0, 1};

    for (int c0 = 0; c0 < C; c0 += CK) {
        const int ck = min(CK, C - c0);
        __syncthreads();

        // ---- load input halo planes (zero padded) ----
        const int halo_elems = ck * HALO_R * HALO_C;
        for (int idx = tid; idx < halo_elems; idx += 256) {
            int c   = idx / (HALO_R * HALO_C);
            int rem = idx - c * (HALO_R * HALO_C);
            int rr  = rem / HALO_C;
            int cc  = rem - rr * HALO_C;
            int gr  = r0 - 2 + rr;
            int gc  = cc - 3;
            float v = 0.f;
            if ((unsigned)gr < (unsigned)HH && (unsigned)gc < (unsigned)WW) {
                int gch = c0 + c;
                const float* p = (gch < CA)
                    ? xA + (((size_t)n * CA + gch) * HH + gr) * WW + gc
                    : xB + (((size_t)n * CB + (gch - CA)) * HH + gr) * WW + gc;
                v = *p;
            }
            xs[c][rem] = v;
        }

        // ---- load weight tile (coalesced: wt is [C][9][O]) ----
        const int w_elems = ck * 9 * TO;
        for (int idx = tid; idx < w_elems; idx += 256) {
            int c   = idx / (9 * TO);
            int rem = idx - c * (9 * TO);
            int t   = rem / TO;
            int o   = rem - t * TO;
            ws[c][t][o] = wt[((size_t)(c0 + c) * 9 + t) * OCH + oBase + o];
        }
        __syncthreads();

        // ---- packed-FMA main loop ----
        for (int c = 0; c < ck; c++) {
#pragma unroll
            for (int t = 0; t < 9; t++) {
                const int toff = tap_dh[t] * HALO_C + tap_dw[t];
                // 8 contiguous weights -> 4 packed f32x2 pairs via two LDS.128
                const ulonglong2* wp = reinterpret_cast<const ulonglong2*>(&ws[c][t][so * 8]);
                ulonglong2 wa = wp[0];
                ulonglong2 wb = wp[1];
                unsigned long long w2[4] = {wa.x, wa.y, wb.x, wb.y};
#pragma unroll
                for (int i = 0; i < 7; i++) {
                    float xv = xs[c][sbase[i] + toff];
                    unsigned long long xv2;
                    asm("mov.b64 %0, {%1, %1};" : "=l"(xv2) : "f"(xv));
#pragma unroll
                    for (int j = 0; j < 4; j++)
                        asm("fma.rn.f32x2 %0, %1, %2, %0;"
                            : "+l"(acc2[i][j]) : "l"(xv2), "l"(w2[j]));
                }
            }
        }
    }

    // ---- store with ReLU ----
#pragma unroll
    for (int i = 0; i < 7; i++) {
        if (!svalid[i]) continue;
        int r = r0 + srow[i];
        int c = scol[i];
#pragma unroll
        for (int j = 0; j < 4; j++) {
            float lo, hi;
            asm("mov.b64 {%0, %1}, %2;" : "=f"(lo), "=f"(hi) : "l"(acc2[i][j]));
            int o = oBase + so * 8 + 2 * j;
            size_t base = (((size_t)n * OCH + o) * HH + r) * WW + c;
            out[base]            = fmaxf(lo, 0.f);
            out[base + HH * WW]  = fmaxf(hi, 0.f);
        }
    }
}

// ---------------------------------------------------------------------------
extern "C" void kernel_launch(void* const* d_in, const int* in_sizes, int n_in,
                              void* d_out, int out_size)
{
    const float* features  = (const float*)d_in[0];   // [128,512,28,28]
    const float* fine_segm = (const float*)d_in[1];   // [128,25,112,112]
    const float* w1 = (const float*)d_in[2];          // [256,537,3,3]
    const float* w2 = (const float*)d_in[3];          // [256,256,3,3]
    const float* w3 = (const float*)d_in[4];
    const float* w4 = (const float*)d_in[5];
    float* out = (float*)d_out;                       // [128,256,28,28]

    float *pooled, *x1, *x2, *w1t, *w2t, *w3t, *w4t;
    cudaGetSymbolAddress((void**)&pooled, g_pooled);
    cudaGetSymbolAddress((void**)&x1, g_x1);
    cudaGetSymbolAddress((void**)&x2, g_x2);
    cudaGetSymbolAddress((void**)&w1t, g_w1t);
    cudaGetSymbolAddress((void**)&w2t, g_w2t);
    cudaGetSymbolAddress((void**)&w3t, g_w3t);
    cudaGetSymbolAddress((void**)&w4t, g_w4t);

    {
        int total = NIMG * CP * HH * WW;
        pool_kernel<<<(total + 255) / 256, 256>>>(fine_segm, pooled);
    }
    repack_kernel<<<(C1 * 9 * OCH + 255) / 256, 256>>>(w1, w1t, C1);
    repack_kernel<<<(OCH * 9 * OCH + 255) / 256, 256>>>(w2, w2t, OCH);
    repack_kernel<<<(OCH * 9 * OCH + 255) / 256, 256>>>(w3, w3t, OCH);
    repack_kernel<<<(OCH * 9 * OCH + 255) / 256, 256>>>(w4, w4t, OCH);

    dim3 grid(4, OCH / TO, NIMG);
    dim3 block(256);

    conv_layer<<<grid, block>>>(features, CF, pooled, CP, w1t, C1, x1);
    conv_layer<<<grid, block>>>(x1, OCH, x1, 1, w2t, OCH, x2);
    conv_layer<<<grid, block>>>(x2, OCH, x2, 1, w3t, OCH, x1);
    conv_layer<<<grid, block>>>(x1, OCH, x1, 1, w4t, OCH, out);
}

// round 7
// speedup vs baseline: 2.8589x; 2.7542x over previous
#include <cuda_runtime.h>
#include <cuda_bf16.h>
#include <cstdint>
#include <math.h>

#define NIMG 128
#define OCH 256
#define C1 537

// SMEM: triple-buffered stage = A(2x16KB hi/lo) + B(2x14KB hi/lo) = 61440 B
#define STG 61440
#define ASM(b,hl) ((b)*STG + (hl)*16384)            // A: 128 rows x 128B
#define BSM(b,hl) ((b)*STG + 32768 + (hl)*14336)    // B: 112 rows x 128B
#define SMEMSZ (3*STG)                              // 184320 B
#define SWZ(x) ((x) ^ (((x)>>3)&0x70))

__device__ __constant__ int c_dh[9] = {-1,-1,-1,0,0,-2,0,2,3};
__device__ __constant__ int c_dw[9] = {-3,-1,1,0,2,1,-1,0,1};

__device__ __align__(128) float         g_pooled[(size_t)NIMG*25*784];
__device__ __align__(128) __nv_bfloat16 g_in [(size_t)NIMG*784*2*576];
__device__ __align__(128) __nv_bfloat16 g_yA [(size_t)NIMG*784*2*256];
__device__ __align__(128) __nv_bfloat16 g_yB [(size_t)NIMG*784*2*256];
__device__ __align__(128) __nv_bfloat16 g_w1p[(size_t)81*2*256*64];
__device__ __align__(128) __nv_bfloat16 g_w2p[(size_t)36*2*256*64];
__device__ __align__(128) __nv_bfloat16 g_w3p[(size_t)36*2*256*64];
__device__ __align__(128) __nv_bfloat16 g_w4p[(size_t)36*2*256*64];

__device__ __forceinline__ uint32_t smem_u32(const void* p) {
    uint32_t a;
    asm("{ .reg .u64 t; cvta.to.shared.u64 t, %1; cvt.u32.u64 %0, t; }" : "=r"(a) : "l"(p));
    return a;
}
__device__ __forceinline__ void cpa(uint32_t dst, const void* src, uint32_t sz) {
    asm volatile("cp.async.cg.shared.global [%0], [%1], 16, %2;" :: "r"(dst), "l"(src), "r"(sz));
}
#define CP_COMMIT() asm volatile("cp.async.commit_group;" ::: "memory")
#define CP_WAIT1()  asm volatile("cp.async.wait_group 1;" ::: "memory")
#define CP_WAIT0()  asm volatile("cp.async.wait_group 0;" ::: "memory")
#define LDSM4(r,a) asm volatile("ldmatrix.sync.aligned.m8n8.x4.shared.b16 {%0,%1,%2,%3}, [%4];" \
    : "=r"((r)[0]),"=r"((r)[1]),"=r"((r)[2]),"=r"((r)[3]) : "r"(a))
#define LDSM2(r,a) asm volatile("ldmatrix.sync.aligned.m8n8.x2.shared.b16 {%0,%1}, [%2];" \
    : "=r"((r)[0]),"=r"((r)[1]) : "r"(a))
#define MMA(d,a,b) asm volatile( \
    "mma.sync.aligned.m16n8k16.row.col.f32.bf16.bf16.f32 {%0,%1,%2,%3}, {%4,%5,%6,%7}, {%8,%9}, {%0,%1,%2,%3};" \
    : "+f"((d)[0]),"+f"((d)[1]),"+f"((d)[2]),"+f"((d)[3]) \
    : "r"((a)[0]),"r"((a)[1]),"r"((a)[2]),"r"((a)[3]),"r"((b)[0]),"r"((b)[1]))

// ---------------- prepass kernels ----------------
__global__ void pool_kernel(const float* __restrict__ in, float* __restrict__ out) {
    int idx = blockIdx.x * blockDim.x + threadIdx.x;
    if (idx >= NIMG*25*784) return;
    int plane = idx / 784, rem = idx % 784;
    int r = rem / 28, c = rem % 28;
    const float* p = in + ((size_t)plane*112 + r*4)*112 + c*4;
    float m = -INFINITY;
#pragma unroll
    for (int i = 0; i < 4; i++)
#pragma unroll
        for (int j = 0; j < 4; j++) m = fmaxf(m, p[i*112+j]);
    out[idx] = m;
}

// features+pooled (NCHW f32) -> g_in [n][pix][hl][576] bf16
__global__ void pack_input(const float* __restrict__ feat, const float* __restrict__ pooled,
                           __nv_bfloat16* __restrict__ out) {
    __shared__ float tile[32][113];
    int pt = blockIdx.x, ct = blockIdx.y, n = blockIdx.z, tid = threadIdx.x;
    for (int idx = tid; idx < 32*112; idx += 256) {
        int cl = idx / 112, pl = idx % 112;
        int c = ct*32 + cl, p = pt*112 + pl;
        float v = 0.f;
        if (c < 512) v = feat[((size_t)n*512 + c)*784 + p];
        else if (c < C1) v = pooled[((size_t)n*25 + (c-512))*784 + p];
        tile[cl][pl] = v;
    }
    __syncthreads();
    for (int idx = tid; idx < 112*32; idx += 256) {
        int pl = idx / 32, cl = idx % 32;
        float v = tile[cl][pl];
        __nv_bfloat16 hi = __float2bfloat16(v);
        __nv_bfloat16 lo = __float2bfloat16(v - __bfloat162float(hi));
        size_t base = ((size_t)n*784 + pt*112 + pl)*2;
        out[(base+0)*576 + ct*32 + cl] = hi;
        out[(base+1)*576 + ct*32 + cl] = lo;
    }
}

// w[o][c][9] f32 -> [stage=chunk*9+t][hl][o][64] bf16
__global__ void pack_w(const float* __restrict__ w, __nv_bfloat16* __restrict__ out,
                       int C, int nChunks) {
    int idx = blockIdx.x * blockDim.x + threadIdx.x;
    if (idx >= nChunks*9*256*64) return;
    int ch = idx & 63, o = (idx >> 6) & 255, t = (idx >> 14) % 9, chunk = idx / (9*16384);
    int c = chunk*64 + ch;
    float v = (c < C) ? w[((size_t)o*C + c)*9 + t] : 0.f;
    __nv_bfloat16 hi = __float2bfloat16(v);
    __nv_bfloat16 lo = __float2bfloat16(v - __bfloat162float(hi));
    size_t b = (((size_t)(chunk*9+t)*2)*256 + o)*64 + ch;
    out[b] = hi;
    out[b + (size_t)256*64] = lo;
}

// ---------------- main HMMA conv layer ----------------
// D[128 o][112 pix] per CTA; stages = chunks x 9 taps; 3-term bf16 split.
__global__ __launch_bounds__(256, 1)
void conv_mma(const __nv_bfloat16* __restrict__ actIn, int CpadIn, int nChunks,
              const __nv_bfloat16* __restrict__ wPack,
              __nv_bfloat16* __restrict__ actOut, float* __restrict__ fOut)
{
    extern __shared__ __align__(1024) char smem[];
    uint32_t sb = smem_u32(smem);
    int tid = threadIdx.x, wid = tid >> 5, lane = tid & 31;
    int rt = blockIdx.x, oBase = blockIdx.y * 128, n = blockIdx.z;
    int r0 = rt * 4;
    int wm = wid & 3, wn = wid >> 2;        // warp tile: 32 o x 56 pix

    const int nStages = nChunks * 9;

    float d[2][7][4];
#pragma unroll
    for (int mi = 0; mi < 2; mi++)
#pragma unroll
        for (int ni = 0; ni < 7; ni++)
#pragma unroll
            for (int k = 0; k < 4; k++) d[mi][ni][k] = 0.f;

    // ---- async fill of one stage into buffer buf ----
    auto fill = [&](int s, int buf) {
        int chunk = s / 9, t = s - chunk*9;
        int dh = c_dh[t], dw = c_dw[t];
        const __nv_bfloat16* wS = wPack + (size_t)s*2*256*64;
#pragma unroll 1
        for (int u = tid; u < 3840; u += 256) {
            if (u < 2048) {            // A: weights, 128 rows x 2 hl x 8 segs
                int o = u >> 4, rem = u & 15, hl = rem >> 3, seg = rem & 7;
                const void* src = wS + (((size_t)hl*256) + oBase + o)*64 + seg*8;
                uint32_t bo = (o << 7) + (seg << 4);
                cpa(sb + ASM(buf,hl) + SWZ(bo), src, 16);
            } else {                   // B: tap-shifted pixels, 112 rows x 2 hl x 8 segs
                int v = u - 2048;
                int i = v >> 4, rem = v & 15, hl = rem >> 3, seg = rem & 7;
                int ri = i / 28;
                int rr = r0 + ri + dh, cc = (i - ri*28) + dw;
                bool ok = ((unsigned)rr < 28u) && ((unsigned)cc < 28u);
                const void* src = actIn +
                    (((size_t)n*784 + (ok ? rr*28 + cc : 0))*2 + hl)*CpadIn + chunk*64 + seg*8;
                uint32_t bo = (i << 7) + (seg << 4);
                cpa(sb + BSM(buf,hl) + SWZ(bo), src, ok ? 16 : 0);
            }
        }
    };

    // ldmatrix address lanes (swizzled rows, byte-column halves)
    int aRow  = (lane & 15);
    int aColb = (lane >> 4) << 4;          // lanes 16-31: k bytes 16..31
    int bRow  = (lane & 7);
    int bColb = ((lane >> 3) & 1) << 4;    // lanes 8-15: k bytes 16..31

    fill(0, 0); CP_COMMIT();

    for (int s = 0; s < nStages; s++) {
        int buf = s % 3;
        if (s + 1 < nStages) { fill(s+1, (s+1)%3); CP_COMMIT(); CP_WAIT1(); }
        else CP_WAIT0();
        __syncthreads();

#pragma unroll
        for (int ks = 0; ks < 4; ks++) {
            uint32_t ah[2][4], al[2][4];
#pragma unroll
            for (int mi = 0; mi < 2; mi++) {
                uint32_t ro = (wm*32 + mi*16 + aRow) << 7;
                uint32_t co = ks*32 + aColb;
                LDSM4(ah[mi], sb + ASM(buf,0) + SWZ(ro + co));
                LDSM4(al[mi], sb + ASM(buf,1) + SWZ(ro + co));
            }
#pragma unroll
            for (int ni = 0; ni < 7; ni++) {
                uint32_t ro = (wn*56 + ni*8 + bRow) << 7;
                uint32_t co = ks*32 + bColb;
                uint32_t bh[2], bl[2];
                LDSM2(bh, sb + BSM(buf,0) + SWZ(ro + co));
                LDSM2(bl, sb + BSM(buf,1) + SWZ(ro + co));
#pragma unroll
                for (int mi = 0; mi < 2; mi++) {
                    MMA(d[mi][ni], ah[mi], bh);
                    MMA(d[mi][ni], ah[mi], bl);
                    MMA(d[mi][ni], al[mi], bh);
                }
            }
        }
        __syncthreads();
    }

    // ---- epilogue: ReLU + store ----
    int quad = lane >> 2, four = lane & 3;
#pragma unroll
    for (int mi = 0; mi < 2; mi++)
#pragma unroll
        for (int ni = 0; ni < 7; ni++)
#pragma unroll
            for (int k = 0; k < 4; k++) {
                float v = fmaxf(d[mi][ni][k], 0.f);
                int o   = oBase + wm*32 + mi*16 + quad + ((k >> 1) << 3);
                int pix = rt*112 + wn*56 + ni*8 + four*2 + (k & 1);
                if (actOut) {
                    __nv_bfloat16 hi = __float2bfloat16(v);
                    __nv_bfloat16 lo = __float2bfloat16(v - __bfloat162float(hi));
                    size_t b = ((size_t)n*784 + pix)*2;
                    actOut[(b+0)*256 + o] = hi;
                    actOut[(b+1)*256 + o] = lo;
                } else {
                    fOut[((size_t)n*256 + o)*784 + pix] = v;
                }
            }
}

// ---------------------------------------------------------------------------
extern "C" void kernel_launch(void* const* d_in, const int* in_sizes, int n_in,
                              void* d_out, int out_size)
{
    const float* features  = (const float*)d_in[0];
    const float* fine_segm = (const float*)d_in[1];
    const float* w1 = (const float*)d_in[2];
    const float* w2 = (const float*)d_in[3];
    const float* w3 = (const float*)d_in[4];
    const float* w4 = (const float*)d_in[5];
    float* out = (float*)d_out;

    float *pooled; __nv_bfloat16 *in, *yA, *yB, *w1p, *w2p, *w3p, *w4p;
    cudaGetSymbolAddress((void**)&pooled, g_pooled);
    cudaGetSymbolAddress((void**)&in,  g_in);
    cudaGetSymbolAddress((void**)&yA,  g_yA);
    cudaGetSymbolAddress((void**)&yB,  g_yB);
    cudaGetSymbolAddress((void**)&w1p, g_w1p);
    cudaGetSymbolAddress((void**)&w2p, g_w2p);
    cudaGetSymbolAddress((void**)&w3p, g_w3p);
    cudaGetSymbolAddress((void**)&w4p, g_w4p);

    cudaFuncSetAttribute(conv_mma, cudaFuncAttributeMaxDynamicSharedMemorySize, SMEMSZ);

    pool_kernel<<<(NIMG*25*784 + 255)/256, 256>>>(fine_segm, pooled);
    pack_input<<<dim3(7,18,NIMG), 256>>>(features, pooled, in);
    pack_w<<<(9*9*16384 + 255)/256, 256>>>(w1, w1p, C1, 9);
    pack_w<<<(4*9*16384 + 255)/256, 256>>>(w2, w2p, 256, 4);
    pack_w<<<(4*9*16384 + 255)/256, 256>>>(w3, w3p, 256, 4);
    pack_w<<<(4*9*16384 + 255)/256, 256>>>(w4, w4p, 256, 4);

    dim3 grid(7, 2, NIMG);
    conv_mma<<<grid, 256, SMEMSZ>>>(in, 576, 9, w1p, yA, nullptr);
    conv_mma<<<grid, 256, SMEMSZ>>>(yA, 256, 4, w2p, yB, nullptr);
    conv_mma<<<grid, 256, SMEMSZ>>>(yB, 256, 4, w3p, yA, nullptr);
    conv_mma<<<grid, 256, SMEMSZ>>>(yA, 256, 4, w4p, nullptr, out);
}

// round 8
// speedup vs baseline: 3.1526x; 1.1027x over previous
#include <cuda_runtime.h>
#include <cuda_bf16.h>
#include <cstdint>
#include <math.h>

#define NIMG 128
#define OCH 256
#define C1 537

// SMEM: triple-buffered stage = A(2x16KB hi/lo) + B(2x14KB hi/lo) = 61440 B
#define STG 61440
#define ASM(b,hl) ((b)*STG + (hl)*16384)            // A: 128 rows x 128B
#define BSM(b,hl) ((b)*STG + 32768 + (hl)*14336)    // B: 112 rows x 128B
#define SMEMSZ (3*STG)                              // 184320 B
#define SWZ(x) ((x) ^ (((x)>>3)&0x70))

__device__ __constant__ int c_dh[9] = {-1,-1,-1,0,0,-2,0,2,3};
__device__ __constant__ int c_dw[9] = {-3,-1,1,0,2,1,-1,0,1};

__device__ __align__(128) float         g_pooled[(size_t)NIMG*25*784];
__device__ __align__(128) __nv_bfloat16 g_in [(size_t)NIMG*784*2*576];
__device__ __align__(128) __nv_bfloat16 g_yA [(size_t)NIMG*784*2*256];
__device__ __align__(128) __nv_bfloat16 g_yB [(size_t)NIMG*784*2*256];
__device__ __align__(128) __nv_bfloat16 g_w1p[(size_t)81*2*256*64];
__device__ __align__(128) __nv_bfloat16 g_w2p[(size_t)36*2*256*64];
__device__ __align__(128) __nv_bfloat16 g_w3p[(size_t)36*2*256*64];
__device__ __align__(128) __nv_bfloat16 g_w4p[(size_t)36*2*256*64];

__device__ __forceinline__ uint32_t smem_u32(const void* p) {
    uint32_t a;
    asm("{ .reg .u64 t; cvta.to.shared.u64 t, %1; cvt.u32.u64 %0, t; }" : "=r"(a) : "l"(p));
    return a;
}
__device__ __forceinline__ void cpa(uint32_t dst, const void* src, uint32_t sz) {
    asm volatile("cp.async.cg.shared.global [%0], [%1], 16, %2;" :: "r"(dst), "l"(src), "r"(sz));
}
#define CP_COMMIT() asm volatile("cp.async.commit_group;" ::: "memory")
#define CP_WAIT1()  asm volatile("cp.async.wait_group 1;" ::: "memory")
#define CP_WAIT0()  asm volatile("cp.async.wait_group 0;" ::: "memory")
#define LDSM4(r,a) asm volatile("ldmatrix.sync.aligned.m8n8.x4.shared.b16 {%0,%1,%2,%3}, [%4];" \
    : "=r"((r)[0]),"=r"((r)[1]),"=r"((r)[2]),"=r"((r)[3]) : "r"(a))
#define LDSM2(r,a) asm volatile("ldmatrix.sync.aligned.m8n8.x2.shared.b16 {%0,%1}, [%2];" \
    : "=r"((r)[0]),"=r"((r)[1]) : "r"(a))
#define MMA(d,a,b) asm volatile( \
    "mma.sync.aligned.m16n8k16.row.col.f32.bf16.bf16.f32 {%0,%1,%2,%3}, {%4,%5,%6,%7}, {%8,%9}, {%0,%1,%2,%3};" \
    : "+f"((d)[0]),"+f"((d)[1]),"+f"((d)[2]),"+f"((d)[3]) \
    : "r"((a)[0]),"r"((a)[1]),"r"((a)[2]),"r"((a)[3]),"r"((b)[0]),"r"((b)[1]))

// ---------------- prepass kernels ----------------
__global__ void pool_kernel(const float* __restrict__ in, float* __restrict__ out) {
    int idx = blockIdx.x * blockDim.x + threadIdx.x;
    if (idx >= NIMG*25*784) return;
    int plane = idx / 784, rem = idx % 784;
    int r = rem / 28, c = rem % 28;
    const float* p = in + ((size_t)plane*112 + r*4)*112 + c*4;
    float m = -INFINITY;
#pragma unroll
    for (int i = 0; i < 4; i++)
#pragma unroll
        for (int j = 0; j < 4; j++) m = fmaxf(m, p[i*112+j]);
    out[idx] = m;
}

// features+pooled (NCHW f32) -> g_in [n][pix][hl][576] bf16
__global__ void pack_input(const float* __restrict__ feat, const float* __restrict__ pooled,
                           __nv_bfloat16* __restrict__ out) {
    __shared__ float tile[32][113];
    int pt = blockIdx.x, ct = blockIdx.y, n = blockIdx.z, tid = threadIdx.x;
    for (int idx = tid; idx < 32*112; idx += 256) {
        int cl = idx / 112, pl = idx % 112;
        int c = ct*32 + cl, p = pt*112 + pl;
        float v = 0.f;
        if (c < 512) v = feat[((size_t)n*512 + c)*784 + p];
        else if (c < C1) v = pooled[((size_t)n*25 + (c-512))*784 + p];
        tile[cl][pl] = v;
    }
    __syncthreads();
    for (int idx = tid; idx < 112*32; idx += 256) {
        int pl = idx / 32, cl = idx % 32;
        float v = tile[cl][pl];
        __nv_bfloat16 hi = __float2bfloat16(v);
        __nv_bfloat16 lo = __float2bfloat16(v - __bfloat162float(hi));
        size_t base = ((size_t)n*784 + pt*112 + pl)*2;
        out[(base+0)*576 + ct*32 + cl] = hi;
        out[(base+1)*576 + ct*32 + cl] = lo;
    }
}

// All 4 weight tensors in one launch: [o][c][9] f32 -> [stage][hl][o][64] bf16
__global__ void pack_w_all(const float* __restrict__ w1, const float* __restrict__ w2,
                           const float* __restrict__ w3, const float* __restrict__ w4,
                           __nv_bfloat16* __restrict__ o1, __nv_bfloat16* __restrict__ o2,
                           __nv_bfloat16* __restrict__ o3, __nv_bfloat16* __restrict__ o4) {
    int idx = blockIdx.x * blockDim.x + threadIdx.x;
    const int SZ1 = 81*16384, SZ = 36*16384;
    const float* w; __nv_bfloat16* out; int C, loc;
    if (idx < SZ1)                { w = w1; out = o1; C = C1;  loc = idx; }
    else if (idx < SZ1 + SZ)      { w = w2; out = o2; C = 256; loc = idx - SZ1; }
    else if (idx < SZ1 + 2*SZ)    { w = w3; out = o3; C = 256; loc = idx - SZ1 - SZ; }
    else if (idx < SZ1 + 3*SZ)    { w = w4; out = o4; C = 256; loc = idx - SZ1 - 2*SZ; }
    else return;
    int ch = loc & 63, o = (loc >> 6) & 255, t = (loc >> 14) % 9, chunk = loc / (9*16384);
    int c = chunk*64 + ch;
    float v = (c < C) ? w[((size_t)o*C + c)*9 + t] : 0.f;
    __nv_bfloat16 hi = __float2bfloat16(v);
    __nv_bfloat16 lo = __float2bfloat16(v - __bfloat162float(hi));
    size_t b = (((size_t)(chunk*9+t)*2)*256 + o)*64 + ch;
    out[b] = hi;
    out[b + (size_t)256*64] = lo;
}

// ---------------- main HMMA conv layer ----------------
// D[128 o][112 pix] per CTA; 512 threads, warp grid 8(m) x 2(n): 16o x 56pix per warp.
__global__ __launch_bounds__(512, 1)
void conv_mma(const __nv_bfloat16* __restrict__ actIn, int CpadIn, int nChunks,
              const __nv_bfloat16* __restrict__ wPack,
              __nv_bfloat16* __restrict__ actOut, float* __restrict__ fOut)
{
    extern __shared__ __align__(1024) char smem[];
    uint32_t sb = smem_u32(smem);
    int tid = threadIdx.x, wid = tid >> 5, lane = tid & 31;
    int rt = blockIdx.x, oBase = blockIdx.y * 128, n = blockIdx.z;
    int r0 = rt * 4;
    int wm = wid & 7, wn = wid >> 3;        // warp tile: 16 o x 56 pix

    const int nStages = nChunks * 9;

    float d[7][4];
#pragma unroll
    for (int ni = 0; ni < 7; ni++)
#pragma unroll
        for (int k = 0; k < 4; k++) d[ni][k] = 0.f;

    auto fill = [&](int s, int buf) {
        int chunk = s / 9, t = s - chunk*9;
        int dh = c_dh[t], dw = c_dw[t];
        const __nv_bfloat16* wS = wPack + (size_t)s*2*256*64;
#pragma unroll 1
        for (int u = tid; u < 3840; u += 512) {
            if (u < 2048) {            // A: weights, 128 rows x 2 hl x 8 segs
                int o = u >> 4, rem = u & 15, hl = rem >> 3, seg = rem & 7;
                const void* src = wS + (((size_t)hl*256) + oBase + o)*64 + seg*8;
                uint32_t bo = (o << 7) + (seg << 4);
                cpa(sb + ASM(buf,hl) + SWZ(bo), src, 16);
            } else {                   // B: tap-shifted pixels, 112 rows x 2 hl x 8 segs
                int v = u - 2048;
                int i = v >> 4, rem = v & 15, hl = rem >> 3, seg = rem & 7;
                int ri = i / 28;
                int rr = r0 + ri + dh, cc = (i - ri*28) + dw;
                bool ok = ((unsigned)rr < 28u) && ((unsigned)cc < 28u);
                const void* src = actIn +
                    (((size_t)n*784 + (ok ? rr*28 + cc : 0))*2 + hl)*CpadIn + chunk*64 + seg*8;
                uint32_t bo = (i << 7) + (seg << 4);
                cpa(sb + BSM(buf,hl) + SWZ(bo), src, ok ? 16 : 0);
            }
        }
    };

    int aRow  = (lane & 15);
    int aColb = (lane >> 4) << 4;
    int bRow  = (lane & 7);
    int bColb = ((lane >> 3) & 1) << 4;

    fill(0, 0); CP_COMMIT();

    for (int s = 0; s < nStages; s++) {
        int buf = s % 3;
        if (s + 1 < nStages) { fill(s+1, (s+1)%3); CP_COMMIT(); CP_WAIT1(); }
        else CP_WAIT0();
        __syncthreads();   // single sync per stage: triple buffer keeps fill(s+1) off live bufs

#pragma unroll
        for (int ks = 0; ks < 4; ks++) {
            uint32_t ah[4], al[4];
            {
                uint32_t ro = (wm*16 + aRow) << 7;
                uint32_t co = ks*32 + aColb;
                LDSM4(ah, sb + ASM(buf,0) + SWZ(ro + co));
                LDSM4(al, sb + ASM(buf,1) + SWZ(ro + co));
            }
#pragma unroll
            for (int ni = 0; ni < 7; ni++) {
                uint32_t ro = (wn*56 + ni*8 + bRow) << 7;
                uint32_t co = ks*32 + bColb;
                uint32_t bh[2], bl[2];
                LDSM2(bh, sb + BSM(buf,0) + SWZ(ro + co));
                LDSM2(bl, sb + BSM(buf,1) + SWZ(ro + co));
                MMA(d[ni], ah, bh);
                MMA(d[ni], ah, bl);
                MMA(d[ni], al, bh);
            }
        }
    }

    // ---- epilogue: ReLU + store ----
    int quad = lane >> 2, four = lane & 3;
#pragma unroll
    for (int ni = 0; ni < 7; ni++)
#pragma unroll
        for (int k = 0; k < 4; k++) {
            float v = fmaxf(d[ni][k], 0.f);
            int o   = oBase + wm*16 + quad + ((k >> 1) << 3);
            int pix = rt*112 + wn*56 + ni*8 + four*2 + (k & 1);
            if (actOut) {
                __nv_bfloat16 hi = __float2bfloat16(v);
                __nv_bfloat16 lo = __float2bfloat16(v - __bfloat162float(hi));
                size_t b = ((size_t)n*784 + pix)*2;
                actOut[(b+0)*256 + o] = hi;
                actOut[(b+1)*256 + o] = lo;
            } else {
                fOut[((size_t)n*256 + o)*784 + pix] = v;
            }
        }
}

// ---------------------------------------------------------------------------
extern "C" void kernel_launch(void* const* d_in, const int* in_sizes, int n_in,
                              void* d_out, int out_size)
{
    const float* features  = (const float*)d_in[0];
    const float* fine_segm = (const float*)d_in[1];
    const float* w1 = (const float*)d_in[2];
    const float* w2 = (const float*)d_in[3];
    const float* w3 = (const float*)d_in[4];
    const float* w4 = (const float*)d_in[5];
    float* out = (float*)d_out;

    float *pooled; __nv_bfloat16 *in, *yA, *yB, *w1p, *w2p, *w3p, *w4p;
    cudaGetSymbolAddress((void**)&pooled, g_pooled);
    cudaGetSymbolAddress((void**)&in,  g_in);
    cudaGetSymbolAddress((void**)&yA,  g_yA);
    cudaGetSymbolAddress((void**)&yB,  g_yB);
    cudaGetSymbolAddress((void**)&w1p, g_w1p);
    cudaGetSymbolAddress((void**)&w2p, g_w2p);
    cudaGetSymbolAddress((void**)&w3p, g_w3p);
    cudaGetSymbolAddress((void**)&w4p, g_w4p);

    cudaFuncSetAttribute(conv_mma, cudaFuncAttributeMaxDynamicSharedMemorySize, SMEMSZ);

    // Launch order: pool(1) pack_input(2) pack_w_all(3) conv1(4) conv2(5) conv3(6) conv4(7)
    // -> ncu -s 5 -c 1 captures conv3 (a real mainloop layer).
    pool_kernel<<<(NIMG*25*784 + 255)/256, 256>>>(fine_segm, pooled);
    pack_input<<<dim3(7,18,NIMG), 256>>>(features, pooled, in);
    {
        int total = (81 + 3*36) * 16384;
        pack_w_all<<<(total + 255)/256, 256>>>(w1, w2, w3, w4, w1p, w2p, w3p, w4p);
    }

    dim3 grid(7, 2, NIMG);
    conv_mma<<<grid, 512, SMEMSZ>>>(in, 576, 9, w1p, yA, nullptr);
    conv_mma<<<grid, 512, SMEMSZ>>>(yA, 256, 4, w2p, yB, nullptr);
    conv_mma<<<grid, 512, SMEMSZ>>>(yB, 256, 4, w3p, yA, nullptr);
    conv_mma<<<grid, 512, SMEMSZ>>>(yA, 256, 4, w4p, nullptr, out);
}

// round 10
// speedup vs baseline: 3.6047x; 1.1434x over previous
#include <cuda_runtime.h>
#include <cuda_bf16.h>
#include <cstdint>
#include <math.h>

#define NIMG 128
#define OCH 256
#define C1 537

// SMEM: double-buffered stage = A(2x32KB hi/lo) + B(2x14KB hi/lo) = 94208 B
#define STG 94208
#define ASM(b,hl) ((b)*STG + (hl)*32768)            // A: 256 rows x 128B
#define BSM(b,hl) ((b)*STG + 65536 + (hl)*14336)    // B: 112 rows x 128B
#define SMEMSZ (2*STG)                              // 188416 B
#define SWZ(x) ((x) ^ (((x)>>3)&0x70))

__device__ __constant__ int c_dh[9] = {-1,-1,-1,0,0,-2,0,2,3};
__device__ __constant__ int c_dw[9] = {-3,-1,1,0,2,1,-1,0,1};

__device__ __align__(128) float         g_pooled[(size_t)NIMG*25*784];
__device__ __align__(128) __nv_bfloat16 g_in [(size_t)NIMG*784*2*576];
__device__ __align__(128) __nv_bfloat16 g_yA [(size_t)NIMG*784*2*256];
__device__ __align__(128) __nv_bfloat16 g_yB [(size_t)NIMG*784*2*256];
__device__ __align__(128) __nv_bfloat16 g_w1p[(size_t)81*2*256*64];
__device__ __align__(128) __nv_bfloat16 g_w2p[(size_t)36*2*256*64];
__device__ __align__(128) __nv_bfloat16 g_w3p[(size_t)36*2*256*64];
__device__ __align__(128) __nv_bfloat16 g_w4p[(size_t)36*2*256*64];

__device__ __forceinline__ uint32_t smem_u32(const void* p) {
    uint32_t a;
    asm("{ .reg .u64 t; cvta.to.shared.u64 t, %1; cvt.u32.u64 %0, t; }" : "=r"(a) : "l"(p));
    return a;
}
__device__ __forceinline__ void cpa(uint32_t dst, const void* src, uint32_t sz) {
    asm volatile("cp.async.cg.shared.global [%0], [%1], 16, %2;" :: "r"(dst), "l"(src), "r"(sz));
}
#define CP_COMMIT() asm volatile("cp.async.commit_group;" ::: "memory")
#define CP_WAIT1()  asm volatile("cp.async.wait_group 1;" ::: "memory")
#define CP_WAIT0()  asm volatile("cp.async.wait_group 0;" ::: "memory")
#define LDSM4(r,a) asm volatile("ldmatrix.sync.aligned.m8n8.x4.shared.b16 {%0,%1,%2,%3}, [%4];" \
    : "=r"((r)[0]),"=r"((r)[1]),"=r"((r)[2]),"=r"((r)[3]) : "r"(a))
#define LDSM2(r,a) asm volatile("ldmatrix.sync.aligned.m8n8.x2.shared.b16 {%0,%1}, [%2];" \
    : "=r"((r)[0]),"=r"((r)[1]) : "r"(a))
#define MMA(d,a,b) asm volatile( \
    "mma.sync.aligned.m16n8k16.row.col.f32.bf16.bf16.f32 {%0,%1,%2,%3}, {%4,%5,%6,%7}, {%8,%9}, {%0,%1,%2,%3};" \
    : "+f"((d)[0]),"+f"((d)[1]),"+f"((d)[2]),"+f"((d)[3]) \
    : "r"((a)[0]),"r"((a)[1]),"r"((a)[2]),"r"((a)[3]),"r"((b)[0]),"r"((b)[1]))

// ---------------- prepass kernels ----------------
__global__ void pool_kernel(const float* __restrict__ in, float* __restrict__ out) {
    int idx = blockIdx.x * blockDim.x + threadIdx.x;
    if (idx >= NIMG*25*784) return;
    int plane = idx / 784, rem = idx % 784;
    int r = rem / 28, c = rem % 28;
    const float* p = in + ((size_t)plane*112 + r*4)*112 + c*4;
    float m = -INFINITY;
#pragma unroll
    for (int i = 0; i < 4; i++)
#pragma unroll
        for (int j = 0; j < 4; j++) m = fmaxf(m, p[i*112+j]);
    out[idx] = m;
}

// features+pooled (NCHW f32) -> g_in [n][pix][hl][576] bf16
__global__ void pack_input(const float* __restrict__ feat, const float* __restrict__ pooled,
                           __nv_bfloat16* __restrict__ out) {
    __shared__ float tile[32][113];
    int pt = blockIdx.x, ct = blockIdx.y, n = blockIdx.z, tid = threadIdx.x;
    for (int idx = tid; idx < 32*112; idx += 256) {
        int cl = idx / 112, pl = idx % 112;
        int c = ct*32 + cl, p = pt*112 + pl;
        float v = 0.f;
        if (c < 512) v = feat[((size_t)n*512 + c)*784 + p];
        else if (c < C1) v = pooled[((size_t)n*25 + (c-512))*784 + p];
        tile[cl][pl] = v;
    }
    __syncthreads();
    for (int idx = tid; idx < 112*32; idx += 256) {
        int pl = idx / 32, cl = idx % 32;
        float v = tile[cl][pl];
        __nv_bfloat16 hi = __float2bfloat16(v);
        __nv_bfloat16 lo = __float2bfloat16(v - __bfloat162float(hi));
        size_t base = ((size_t)n*784 + pt*112 + pl)*2;
        out[(base+0)*576 + ct*32 + cl] = hi;
        out[(base+1)*576 + ct*32 + cl] = lo;
    }
}

// All 4 weight tensors in one launch: [o][c][9] f32 -> [stage][hl][o][64] bf16
__global__ void pack_w_all(const float* __restrict__ w1, const float* __restrict__ w2,
                           const float* __restrict__ w3, const float* __restrict__ w4,
                           __nv_bfloat16* __restrict__ o1, __nv_bfloat16* __restrict__ o2,
                           __nv_bfloat16* __restrict__ o3, __nv_bfloat16* __restrict__ o4) {
    int idx = blockIdx.x * blockDim.x + threadIdx.x;
    const int SZ1 = 81*16384, SZ = 36*16384;
    const float* w; __nv_bfloat16* out; int C, loc;
    if (idx < SZ1)                { w = w1; out = o1; C = C1;  loc = idx; }
    else if (idx < SZ1 + SZ)      { w = w2; out = o2; C = 256; loc = idx - SZ1; }
    else if (idx < SZ1 + 2*SZ)    { w = w3; out = o3; C = 256; loc = idx - SZ1 - SZ; }
    else if (idx < SZ1 + 3*SZ)    { w = w4; out = o4; C = 256; loc = idx - SZ1 - 2*SZ; }
    else return;
    int ch = loc & 63, o = (loc >> 6) & 255, t = (loc >> 14) % 9, chunk = loc / (9*16384);
    int c = chunk*64 + ch;
    float v = (c < C) ? w[((size_t)o*C + c)*9 + t] : 0.f;
    __nv_bfloat16 hi = __float2bfloat16(v);
    __nv_bfloat16 lo = __float2bfloat16(v - __bfloat162float(hi));
    size_t b = (((size_t)(chunk*9+t)*2)*256 + o)*64 + ch;
    out[b] = hi;
    out[b + (size_t)256*64] = lo;
}

// ---------------- main HMMA conv layer ----------------
// D[256 o][112 pix] per CTA; 512 threads, warp grid 8(m) x 2(n): 32o x 56pix per warp.
// B fragments amortized over 2 m-tiles -> ldsm traffic off the critical path.
__global__ __launch_bounds__(512, 1)
void conv_mma(const __nv_bfloat16* __restrict__ actIn, int CpadIn, int nChunks,
              const __nv_bfloat16* __restrict__ wPack,
              __nv_bfloat16* __restrict__ actOut, float* __restrict__ fOut)
{
    extern __shared__ __align__(1024) char smem[];
    uint32_t sb = smem_u32(smem);
    int tid = threadIdx.x, wid = tid >> 5, lane = tid & 31;
    int rt = blockIdx.x, n = blockIdx.z;
    int r0 = rt * 4;
    int wm = wid & 7, wn = wid >> 3;        // warp tile: 32 o x 56 pix

    const int nStages = nChunks * 9;

    float d[2][7][4];
#pragma unroll
    for (int mi = 0; mi < 2; mi++)
#pragma unroll
        for (int ni = 0; ni < 7; ni++)
#pragma unroll
            for (int k = 0; k < 4; k++) d[mi][ni][k] = 0.f;

    auto fill = [&](int s, int buf) {
        int chunk = s / 9, t = s - chunk*9;
        int dh = c_dh[t], dw = c_dw[t];
        const __nv_bfloat16* wS = wPack + (size_t)s*2*256*64;
#pragma unroll 1
        for (int u = tid; u < 5888; u += 512) {
            if (u < 4096) {            // A: weights, 256 rows x 2 hl x 8 segs
                int o = u >> 4, rem = u & 15, hl = rem >> 3, seg = rem & 7;
                const void* src = wS + (((size_t)hl*256) + o)*64 + seg*8;
                uint32_t bo = (o << 7) + (seg << 4);
                cpa(sb + ASM(buf,hl) + SWZ(bo), src, 16);
            } else {                   // B: tap-shifted pixels, 112 rows x 2 hl x 8 segs
                int v = u - 4096;
                int i = v >> 4, rem = v & 15, hl = rem >> 3, seg = rem & 7;
                int ri = i / 28;
                int rr = r0 + ri + dh, cc = (i - ri*28) + dw;
                bool ok = ((unsigned)rr < 28u) && ((unsigned)cc < 28u);
                const void* src = actIn +
                    (((size_t)n*784 + (ok ? rr*28 + cc : 0))*2 + hl)*CpadIn + chunk*64 + seg*8;
                uint32_t bo = (i << 7) + (seg << 4);
                cpa(sb + BSM(buf,hl) + SWZ(bo), src, ok ? 16 : 0);
            }
        }
    };

    int aRow  = (lane & 15);
    int aColb = (lane >> 4) << 4;
    int bRow  = (lane & 7);
    int bColb = ((lane >> 3) & 1) << 4;

    fill(0, 0); CP_COMMIT();

    for (int s = 0; s < nStages; s++) {
        int buf = s & 1;
        if (s + 1 < nStages) { fill(s+1, buf ^ 1); CP_COMMIT(); CP_WAIT1(); }
        else CP_WAIT0();
        __syncthreads();

#pragma unroll
        for (int ks = 0; ks < 4; ks++) {
            uint32_t ah[2][4], al[2][4];
#pragma unroll
            for (int mi = 0; mi < 2; mi++) {
                uint32_t ro = (wm*32 + mi*16 + aRow) << 7;
                uint32_t co = ks*32 + aColb;
                LDSM4(ah[mi], sb + ASM(buf,0) + SWZ(ro + co));
                LDSM4(al[mi], sb + ASM(buf,1) + SWZ(ro + co));
            }
#pragma unroll
            for (int ni = 0; ni < 7; ni++) {
                uint32_t ro = (wn*56 + ni*8 + bRow) << 7;
                uint32_t co = ks*32 + bColb;
                uint32_t bh[2], bl[2];
                LDSM2(bh, sb + BSM(buf,0) + SWZ(ro + co));
                LDSM2(bl, sb + BSM(buf,1) + SWZ(ro + co));
#pragma unroll
                for (int mi = 0; mi < 2; mi++) {
                    MMA(d[mi][ni], ah[mi], bh);
                    MMA(d[mi][ni], ah[mi], bl);
                    MMA(d[mi][ni], al[mi], bh);
                }
            }
        }
        __syncthreads();   // double buffer: next fill overwrites buf^1 -> all readers must be done
    }

    // ---- epilogue: ReLU + store ----
    int quad = lane >> 2, four = lane & 3;
#pragma unroll
    for (int mi = 0; mi < 2; mi++)
#pragma unroll
        for (int ni = 0; ni < 7; ni++)
#pragma unroll
            for (int k = 0; k < 4; k++) {
                float v = fmaxf(d[mi][ni][k], 0.f);
                int o   = wm*32 + mi*16 + quad + ((k >> 1) << 3);
                int pix = rt*112 + wn*56 + ni*8 + four*2 + (k & 1);
                if (actOut) {
                    __nv_bfloat16 hi = __float2bfloat16(v);
                    __nv_bfloat16 lo = __float2bfloat16(v - __bfloat162float(hi));
                    size_t b = ((size_t)n*784 + pix)*2;
                    actOut[(b+0)*256 + o] = hi;
                    actOut[(b+1)*256 + o] = lo;
                } else {
                    fOut[((size_t)n*256 + o)*784 + pix] = v;
                }
            }
}

// ---------------------------------------------------------------------------
extern "C" void kernel_launch(void* const* d_in, const int* in_sizes, int n_in,
                              void* d_out, int out_size)
{
    const float* features  = (const float*)d_in[0];
    const float* fine_segm = (const float*)d_in[1];
    const float* w1 = (const float*)d_in[2];
    const float* w2 = (const float*)d_in[3];
    const float* w3 = (const float*)d_in[4];
    const float* w4 = (const float*)d_in[5];
    float* out = (float*)d_out;

    float *pooled; __nv_bfloat16 *in, *yA, *yB, *w1p, *w2p, *w3p, *w4p;
    cudaGetSymbolAddress((void**)&pooled, g_pooled);
    cudaGetSymbolAddress((void**)&in,  g_in);
    cudaGetSymbolAddress((void**)&yA,  g_yA);
    cudaGetSymbolAddress((void**)&yB,  g_yB);
    cudaGetSymbolAddress((void**)&w1p, g_w1p);
    cudaGetSymbolAddress((void**)&w2p, g_w2p);
    cudaGetSymbolAddress((void**)&w3p, g_w3p);
    cudaGetSymbolAddress((void**)&w4p, g_w4p);

    cudaFuncSetAttribute(conv_mma, cudaFuncAttributeMaxDynamicSharedMemorySize, SMEMSZ);

    pool_kernel<<<(NIMG*25*784 + 255)/256, 256>>>(fine_segm, pooled);
    pack_input<<<dim3(7,18,NIMG), 256>>>(features, pooled, in);
    {
        int total = (81 + 3*36) * 16384;
        pack_w_all<<<(total + 255)/256, 256>>>(w1, w2, w3, w4, w1p, w2p, w3p, w4p);
    }

    dim3 grid(7, 1, NIMG);
    conv_mma<<<grid, 512, SMEMSZ>>>(in, 576, 9, w1p, yA, nullptr);
    conv_mma<<<grid, 512, SMEMSZ>>>(yA, 256, 4, w2p, yB, nullptr);
    conv_mma<<<grid, 512, SMEMSZ>>>(yB, 256, 4, w3p, yA, nullptr);
    conv_mma<<<grid, 512, SMEMSZ>>>(yA, 256, 4, w4p, nullptr, out);
}